// round 8
// baseline (speedup 1.0000x reference)
#include <cuda_runtime.h>
#include <cuda_bf16.h>
#include <math.h>
#include <stdint.h>

#define D_DIM 512
#define K_CODES 4096
#define N_TOK 32768
#define NT 32           // 32 code tiles of 128

// fp8 quantization scales
#define SX 32.0f
#define SW 131072.0f
#define DEQ (1.0f / (SX * SW))     // 2^-22

// ---------------- device scratch (no allocations allowed) ----------------
__device__ int    g_indices[N_TOK];
__device__ int    g_counts[K_CODES];
__device__ float  g_wnorm[K_CODES];
__device__ float  g_xnorm[N_TOK];
__device__ uint8_t g_Xq[(size_t)N_TOK * D_DIM];    // e4m3
__device__ uint8_t g_Wq[(size_t)K_CODES * D_DIM];  // e4m3
__device__ float4 g_cand[(size_t)N_TOK * NT * 2];  // per (row,tile): best-4 {d,i} pairs

// ---------------- PTX helpers (baseline ISA only: sm_89+) ----------------
__device__ __forceinline__ uint32_t smem_to_u32(const void* p) {
    uint32_t a;
    asm("{ .reg .u64 t; cvta.to.shared.u64 t, %1; cvt.u32.u64 %0, t; }" : "=r"(a) : "l"(p));
    return a;
}
#define LDSM_X4(r0, r1, r2, r3, addr) \
    asm volatile("ldmatrix.sync.aligned.m8n8.x4.shared.b16 {%0,%1,%2,%3}, [%4];" \
        : "=r"(r0), "=r"(r1), "=r"(r2), "=r"(r3) : "r"(addr))
#define MMA16832_FP8(d, a, b) \
    asm volatile("mma.sync.aligned.m16n8k32.row.col.f32.e4m3.e4m3.f32 " \
        "{%0,%1,%2,%3},{%4,%5,%6,%7},{%8,%9},{%0,%1,%2,%3};" \
        : "+f"((d)[0]), "+f"((d)[1]), "+f"((d)[2]), "+f"((d)[3]) \
        : "r"((a)[0]), "r"((a)[1]), "r"((a)[2]), "r"((a)[3]), "r"((b)[0]), "r"((b)[1]))
#define CP_ASYNC16(dst, src) \
    asm volatile("cp.async.cg.shared.global [%0], [%1], 16;" :: "r"(dst), "l"(src))
#define CP_COMMIT() asm volatile("cp.async.commit_group;" ::: "memory")
#define CP_WAIT0()  asm volatile("cp.async.wait_group 0;" ::: "memory")

// pack two floats to e4m3x2: result byte0 = cvt(lo), byte1 = cvt(hi)
__device__ __forceinline__ uint16_t pack_e4m3x2(float hi, float lo) {
    uint16_t r;
    asm("cvt.rn.satfinite.e4m3x2.f32 %0, %1, %2;" : "=h"(r) : "f"(hi), "f"(lo));
    return r;
}

// dynamic smem layout for stage1 (bytes)
#define S_MERGE 0                    // 8 KB  [128 rows][4 quadrants] float4 (top-2 each)
#define S_A     8192                 // 64 KB A resident (128 x 512 e4m3, swizzled)
#define S_B0    (S_A + 65536)        // 73728, 16 KB
#define S_B1    (S_B0 + 16384)       // 90112, 16 KB
#define S_TOT   (S_B1 + 16384)       // 106496

// ---------------- convert kernels (fp32 -> e4m3) ----------------
__global__ void cvtX_kernel(const float* __restrict__ X) {
    int i = blockIdx.x * blockDim.x + threadIdx.x;      // float4 index
    if (i >= N_TOK * D_DIM / 4) return;
    float4 v = ((const float4*)X)[i];
    uint32_t lo = pack_e4m3x2(v.y * SX, v.x * SX);
    uint32_t hi = pack_e4m3x2(v.w * SX, v.z * SX);
    ((uint32_t*)g_Xq)[i] = lo | (hi << 16);
}
__global__ void cvtW_kernel(const float* __restrict__ W) {
    int i = blockIdx.x * blockDim.x + threadIdx.x;
    if (i >= K_CODES * D_DIM / 4) return;
    float4 v = ((const float4*)W)[i];
    uint32_t lo = pack_e4m3x2(v.y * SW, v.x * SW);
    uint32_t hi = pack_e4m3x2(v.w * SW, v.z * SW);
    ((uint32_t*)g_Wq)[i] = lo | (hi << 16);
}

// ---------------- norm kernel (sequential fadd(fmul) per row — validated R3) ----------------
__global__ void norm_kernel(const float* __restrict__ src, int which) {
    extern __shared__ float s[];               // [64][513]
    int r0 = blockIdx.x * 64;
    const float4* g = (const float4*)(src + (size_t)r0 * D_DIM);
    for (int u = threadIdx.x; u < 64 * 128; u += 256) {
        int row = u >> 7, c4 = u & 127;
        float4 v = g[(size_t)row * 128 + c4];
        float* p = s + row * 513 + c4 * 4;
        p[0] = v.x; p[1] = v.y; p[2] = v.z; p[3] = v.w;
    }
    __syncthreads();
    if (threadIdx.x < 64) {
        const float* p = s + threadIdx.x * 513;
        float acc = 0.f;
        #pragma unroll 8
        for (int i = 0; i < D_DIM; i++)
            acc = __fadd_rn(acc, __fmul_rn(p[i], p[i]));
        if (which) g_xnorm[r0 + threadIdx.x] = acc;
        else       g_wnorm[r0 + threadIdx.x] = acc;
    }
}

// ---------------- stage1: fp8 mma.sync GEMM + per-quadrant top-2 (512 threads) ----------------
// B chunk g (0..NT*4-1): tile t = g>>2, k-chunk kc = g&3 (128 fp8 of K, 16KB).
__device__ __forceinline__ void issue_chunk(uint32_t sb, int tid, int g) {
    int t = g >> 2, kc = g & 3;
    const uint8_t* src = g_Wq + (size_t)(t * 128) * D_DIM + kc * 128;
    uint32_t buf = sb + ((g & 1) ? S_B1 : S_B0);
    #pragma unroll
    for (int i = 0; i < 2; i++) {
        int unit = i * 512 + tid;            // 1024 16B units
        int nrow = unit >> 3, u = unit & 7;
        uint32_t dst = buf + nrow * 128 + ((u ^ (nrow & 7)) << 4);
        const void* gsrc = src + (size_t)nrow * D_DIM + u * 16;
        CP_ASYNC16(dst, gsrc);
    }
    CP_COMMIT();
}

#define CE(i, j) { if (d[j] < d[i]) { float td = d[i]; d[i] = d[j]; d[j] = td; \
                                      int ti = ix[i]; ix[i] = ix[j]; ix[j] = ti; } }

__global__ void __launch_bounds__(512, 1) stage1_kernel() {
    extern __shared__ char smem[];
    const uint32_t sb = smem_to_u32(smem);
    const int tid = threadIdx.x;
    const int lane = tid & 31;
    const int w = tid >> 5;                // 16 warps
    const int wm = w & 3, wn = w >> 2;     // warp tile: rows wm*32, cols wn*32
    const int m0 = blockIdx.x * 128;

    // A resident: 128 rows x 512 e4m3 (512B/row), swizzle u^(r&7), u 0..31
    {
        const uint8_t* Xr = g_Xq + (size_t)m0 * D_DIM;
        #pragma unroll 4
        for (int it = 0; it < 8; it++) {
            int unit = it * 512 + tid;           // 4096 16B units
            int r = unit >> 5, u = unit & 31;
            uint4 v = *(const uint4*)(Xr + (size_t)r * D_DIM + u * 16);
            *(uint4*)(smem + S_A + r * 512 + ((u ^ (r & 7)) << 4)) = v;
        }
    }

    issue_chunk(sb, tid, 0);

    // per-lane ldmatrix addressing (byte layout validated in R6 int8 kernel)
    const int a_row = (lane & 7) + ((lane >> 3) & 1) * 8;
    const int a_kh  = (lane >> 4) & 1;
    uint32_t a_base[2]; int a_x[2];
    #pragma unroll
    for (int mt = 0; mt < 2; mt++) {
        int r = wm * 32 + mt * 16 + a_row;
        a_base[mt] = sb + S_A + r * 512;
        a_x[mt] = r & 7;
    }
    const int b_row_in = (lane & 7) + ((lane >> 4) & 1) * 8;
    const int b_kh     = (lane >> 3) & 1;
    uint32_t b_rowoff[2]; int b_x[2];
    #pragma unroll
    for (int p = 0; p < 2; p++) {
        int nr = wn * 32 + p * 16 + b_row_in;
        b_rowoff[p] = nr * 128;
        b_x[p] = nr & 7;
    }

    const int tg = lane & 3, g8 = lane >> 2;

    for (int t = 0; t < NT; t++) {
        float acc[2][4][4];
        #pragma unroll
        for (int mt = 0; mt < 2; mt++)
            #pragma unroll
            for (int nt = 0; nt < 4; nt++)
                #pragma unroll
                for (int e = 0; e < 4; e++) acc[mt][nt][e] = 0.f;

        for (int kc = 0; kc < 4; kc++) {
            int g = t * 4 + kc;
            CP_WAIT0();
            __syncthreads();
            if (g + 1 < NT * 4) issue_chunk(sb, tid, g + 1);
            uint32_t bbuf = sb + ((g & 1) ? S_B1 : S_B0);
            #pragma unroll
            for (int s = 0; s < 4; s++) {           // 4 k32-steps per 128-k chunk
                int gk = kc * 4 + s;                 // global k32 index 0..15
                uint32_t a[2][4];
                #pragma unroll
                for (int mt = 0; mt < 2; mt++) {
                    int u = gk * 2 + a_kh;           // 16B-unit 0..31
                    LDSM_X4(a[mt][0], a[mt][1], a[mt][2], a[mt][3],
                            a_base[mt] + ((u ^ a_x[mt]) << 4));
                }
                uint32_t b[4][2];
                #pragma unroll
                for (int p = 0; p < 2; p++) {
                    int u = s * 2 + b_kh;            // unit within chunk 0..7
                    uint32_t r0, r1, r2, r3;
                    LDSM_X4(r0, r1, r2, r3, bbuf + b_rowoff[p] + ((u ^ b_x[p]) << 4));
                    b[2 * p][0] = r0; b[2 * p][1] = r1;
                    b[2 * p + 1][0] = r2; b[2 * p + 1][1] = r3;
                }
                #pragma unroll
                for (int mt = 0; mt < 2; mt++)
                    #pragma unroll
                    for (int nt = 0; nt < 4; nt++)
                        MMA16832_FP8(acc[mt][nt], a[mt], b[nt]);
            }
        }

        // ---- per-quadrant (32 codes) top-2 epilogue ----
        float wn8[8];
        #pragma unroll
        for (int nt = 0; nt < 4; nt++)
            #pragma unroll
            for (int e = 0; e < 2; e++)
                wn8[nt * 2 + e] = g_wnorm[t * 128 + wn * 32 + nt * 8 + tg * 2 + e];

        #pragma unroll
        for (int mt = 0; mt < 2; mt++) {
            #pragma unroll
            for (int h = 0; h < 2; h++) {
                float v1 = 3.4e38f, v2 = 3.4e38f; int i1 = 0, i2 = 0;
                #pragma unroll
                for (int nt = 0; nt < 4; nt++) {
                    #pragma unroll
                    for (int e = 0; e < 2; e++) {
                        int code = t * 128 + wn * 32 + nt * 8 + tg * 2 + e;
                        float d = __fmaf_rn(-2.0f * DEQ, acc[mt][nt][h * 2 + e],
                                            wn8[nt * 2 + e]);
                        if (d < v2) {
                            if (d < v1) { v2 = v1; i2 = i1; v1 = d; i1 = code; }
                            else        { v2 = d; i2 = code; }
                        }
                    }
                }
                #pragma unroll
                for (int off = 1; off <= 2; off <<= 1) {
                    float w1 = __shfl_xor_sync(0xffffffffu, v1, off);
                    int   j1 = __shfl_xor_sync(0xffffffffu, i1, off);
                    float w2 = __shfl_xor_sync(0xffffffffu, v2, off);
                    int   j2 = __shfl_xor_sync(0xffffffffu, i2, off);
                    if (w1 < v1) {
                        float nv2; int ni2;
                        if (v1 < w2) { nv2 = v1; ni2 = i1; } else { nv2 = w2; ni2 = j2; }
                        v1 = w1; i1 = j1; v2 = nv2; i2 = ni2;
                    } else if (w1 < v2) { v2 = w1; i2 = j1; }
                }
                if (tg == 0) {
                    int row = wm * 32 + mt * 16 + h * 8 + g8;
                    ((float4*)(smem + S_MERGE))[row * 4 + wn] =
                        make_float4(v1, __int_as_float(i1), v2, __int_as_float(i2));
                }
            }
        }
        __syncthreads();
        if (tid < 128) {
            // merge 4 quadrant top-2 lists -> best 4 of 8 via sort network
            float d[8]; int ix[8];
            #pragma unroll
            for (int q = 0; q < 4; q++) {
                float4 r = ((float4*)(smem + S_MERGE))[tid * 4 + q];
                d[2 * q]     = r.x; ix[2 * q]     = __float_as_int(r.y);
                d[2 * q + 1] = r.z; ix[2 * q + 1] = __float_as_int(r.w);
            }
            CE(0,1) CE(2,3) CE(4,5) CE(6,7)
            CE(0,2) CE(1,3) CE(4,6) CE(5,7)
            CE(1,2) CE(5,6)
            CE(0,4) CE(1,5) CE(2,6) CE(3,7)
            CE(2,4) CE(3,5)
            CE(1,2) CE(3,4) CE(5,6)
            size_t base = ((size_t)(m0 + tid) * NT + t) * 2;
            g_cand[base]     = make_float4(d[0], __int_as_float(ix[0]),
                                           d[1], __int_as_float(ix[1]));
            g_cand[base + 1] = make_float4(d[2], __int_as_float(ix[2]),
                                           d[3], __int_as_float(ix[3]));
        }
        __syncthreads();
    }
}

// ---------------- stage 2: top-8 of 128 + exact fp32 rescore ----------------
__global__ void __launch_bounds__(256) stage2_kernel(const float* __restrict__ X,
                                                     const float* __restrict__ W) {
    const int warp = threadIdx.x >> 5, lane = threadIdx.x & 31;
    const int token = blockIdx.x * 8 + warp;
    const unsigned FULL = 0xffffffffu;

    size_t base = ((size_t)token * NT + lane) * 2;
    float4 ca = g_cand[base];
    float4 cb = g_cand[base + 1];
    float cd0 = ca.x; int ci0 = __float_as_int(ca.y);
    float cd1 = ca.z; int ci1 = __float_as_int(ca.w);
    float cd2 = cb.x; int ci2 = __float_as_int(cb.y);
    float cd3 = cb.z; int ci3 = __float_as_int(cb.w);

    float xr[16];
    const float* x = X + (size_t)token * D_DIM;
    #pragma unroll
    for (int j = 0; j < 4; j++) {
        float4 v = *(const float4*)(x + j * 128 + lane * 4);
        xr[j * 4 + 0] = v.x; xr[j * 4 + 1] = v.y; xr[j * 4 + 2] = v.z; xr[j * 4 + 3] = v.w;
    }
    float xn = g_xnorm[token];
    float bd = 3.4e38f; int bi = 0x7fffffff;

    #pragma unroll
    for (int s = 0; s < 8; s++) {
        float md = fminf(fminf(cd0, cd1), fminf(cd2, cd3));
        float m = md;
        #pragma unroll
        for (int o = 16; o > 0; o >>= 1) m = fminf(m, __shfl_xor_sync(FULL, m, o));
        unsigned ball = __ballot_sync(FULL, md == m);
        int src = __ffs(ball) - 1;
        int pick = 0;
        if (lane == src) {
            if (cd0 == md)      { pick = ci0; cd0 = 3.4e38f; }
            else if (cd1 == md) { pick = ci1; cd1 = 3.4e38f; }
            else if (cd2 == md) { pick = ci2; cd2 = 3.4e38f; }
            else                { pick = ci3; cd3 = 3.4e38f; }
        }
        pick = __shfl_sync(FULL, pick, src);

        const float* wv = W + (size_t)pick * D_DIM;
        float acc = 0.f;
        #pragma unroll
        for (int j = 0; j < 4; j++) {
            float4 v = *(const float4*)(wv + j * 128 + lane * 4);
            acc = __fmaf_rn(xr[j * 4 + 0], v.x, acc);
            acc = __fmaf_rn(xr[j * 4 + 1], v.y, acc);
            acc = __fmaf_rn(xr[j * 4 + 2], v.z, acc);
            acc = __fmaf_rn(xr[j * 4 + 3], v.w, acc);
        }
        #pragma unroll
        for (int o = 16; o > 0; o >>= 1) acc += __shfl_xor_sync(FULL, acc, o);
        float dd = __fsub_rn(__fadd_rn(xn, g_wnorm[pick]), 2.0f * acc);
        if (dd < bd || (dd == bd && pick < bi)) { bd = dd; bi = pick; }
    }
    if (lane == 0) g_indices[token] = bi;
}

// ---------------- output epilogue / histogram / perplexity ----------------
__global__ void epilogue_kernel(const float* __restrict__ X, const float* __restrict__ W,
                                float* __restrict__ out_q, float* __restrict__ out_loss,
                                float* __restrict__ out_idx, int write_loss, int write_idx)
{
    int t = blockIdx.x;
    int idx = g_indices[t];
    const float4* w = (const float4*)(W + (size_t)idx * D_DIM);
    const float4* x = (const float4*)(X + (size_t)t * D_DIM);
    float4* oq = (float4*)(out_q + (size_t)t * D_DIM);

    int c = threadIdx.x;
    float4 qv = w[c];
    float4 xv = x[c];
    float dx = __fsub_rn(qv.x, xv.x), dy = __fsub_rn(qv.y, xv.y);
    float dz = __fsub_rn(qv.z, xv.z), dw = __fsub_rn(qv.w, xv.w);
    float4 st;
    st.x = __fadd_rn(xv.x, dx); st.y = __fadd_rn(xv.y, dy);
    st.z = __fadd_rn(xv.z, dz); st.w = __fadd_rn(xv.w, dw);
    oq[c] = st;
    float s = dx * dx + dy * dy + dz * dz + dw * dw;

    #pragma unroll
    for (int o = 16; o > 0; o >>= 1) s += __shfl_down_sync(0xffffffffu, s, o);
    __shared__ float ws[4];
    if ((threadIdx.x & 31) == 0) ws[threadIdx.x >> 5] = s;
    __syncthreads();
    if (threadIdx.x == 0) {
        float tot = ws[0] + ws[1] + ws[2] + ws[3];
        if (write_loss) out_loss[t] = 1.25f * tot * (1.0f / D_DIM);
        if (write_idx)  out_idx[t] = (float)idx;
    }
}
__global__ void zero_counts_kernel() {
    int i = blockIdx.x * blockDim.x + threadIdx.x;
    if (i < K_CODES) g_counts[i] = 0;
}
__global__ void hist_kernel(int M) {
    int i = blockIdx.x * blockDim.x + threadIdx.x;
    if (i < M) atomicAdd(&g_counts[g_indices[i]], 1);
}
__global__ void perplexity_kernel(float* __restrict__ out_perp, int M) {
    __shared__ float ws[32];
    float inv = 1.0f / (float)M;
    float s = 0.f;
    for (int i = threadIdx.x; i < K_CODES; i += blockDim.x) {
        float p = (float)g_counts[i] * inv;
        s += p * logf(p + 1e-10f);
    }
    #pragma unroll
    for (int o = 16; o > 0; o >>= 1) s += __shfl_down_sync(0xffffffffu, s, o);
    if ((threadIdx.x & 31) == 0) ws[threadIdx.x >> 5] = s;
    __syncthreads();
    if (threadIdx.x == 0) {
        float tot = 0.f;
        int nw = blockDim.x >> 5;
        for (int w = 0; w < nw; w++) tot += ws[w];
        *out_perp = expf(-tot);
    }
}

// ---------------- launch ----------------
extern "C" void kernel_launch(void* const* d_in, const int* in_sizes, int n_in,
                              void* d_out, int out_size)
{
    const float* X = (const float*)d_in[0];   // flat_input [32768, 512]
    const float* W = (const float*)d_in[1];   // weight [4096, 512]
    const int M = in_sizes[0] / D_DIM;

    float* out = (float*)d_out;
    float* out_q = out;
    size_t base = (size_t)M * D_DIM;
    int has_loss = out_size >= (int)(base + M);
    int has_perp = out_size >= (int)(base + M + 1);
    int has_idx  = out_size >= (int)(base + 2 * M + 1);
    float* out_loss = out + base;
    float* out_perp = out_loss + M;
    float* out_idx  = out_perp + 1;

    cudaFuncSetAttribute(stage1_kernel, cudaFuncAttributeMaxDynamicSharedMemorySize, S_TOT);
    cudaFuncSetAttribute(norm_kernel, cudaFuncAttributeMaxDynamicSharedMemorySize, 64 * 513 * 4);

    cvtX_kernel<<<(N_TOK * D_DIM / 4 + 255) / 256, 256>>>(X);
    cvtW_kernel<<<(K_CODES * D_DIM / 4 + 255) / 256, 256>>>(W);
    norm_kernel<<<M / 64, 256, 64 * 513 * 4>>>(X, 1);        // xnorm
    norm_kernel<<<K_CODES / 64, 256, 64 * 513 * 4>>>(W, 0);  // wnorm
    stage1_kernel<<<M / 128, 512, S_TOT>>>();
    stage2_kernel<<<M / 8, 256>>>(X, W);
    epilogue_kernel<<<M, 128>>>(X, W, out_q,
                                has_loss ? out_loss : out_q,
                                has_idx ? out_idx : out_q,
                                has_loss, has_idx);
    if (has_perp) {
        zero_counts_kernel<<<(K_CODES + 255) / 256, 256>>>();
        hist_kernel<<<(M + 255) / 256, 256>>>(M);
        perplexity_kernel<<<1, 1024>>>(out_perp, M);
    }
}

// round 9
// speedup vs baseline: 1.1346x; 1.1346x over previous
#include <cuda_runtime.h>
#include <math.h>
#include <stdint.h>

#define D_DIM 512
#define K_CODES 4096
#define N_TOK 32768
#define NT 32           // 32 code tiles of 128
#define NITEM 2048      // 256 m-tiles x 8 groups (512 codes each)

// fp8 quantization scales
#define SX 32.0f
#define SW 131072.0f
#define DEQ (1.0f / (SX * SW))     // 2^-22

// ---------------- device scratch (no allocations allowed) ----------------
__device__ int    g_indices[N_TOK];
__device__ int    g_counts[K_CODES];
__device__ float  g_wnorm[K_CODES];
__device__ float  g_xnorm[N_TOK];
__device__ uint8_t g_Xq[(size_t)N_TOK * D_DIM];    // e4m3
__device__ uint8_t g_Wq[(size_t)K_CODES * D_DIM];  // e4m3
__device__ float4 g_cand[(size_t)N_TOK * NT * 2];  // per (row,tile): best-4 {d,i} pairs

// ---------------- PTX helpers (baseline ISA only: sm_89+) ----------------
__device__ __forceinline__ uint32_t smem_to_u32(const void* p) {
    uint32_t a;
    asm("{ .reg .u64 t; cvta.to.shared.u64 t, %1; cvt.u32.u64 %0, t; }" : "=r"(a) : "l"(p));
    return a;
}
#define LDSM_X4(r0, r1, r2, r3, addr) \
    asm volatile("ldmatrix.sync.aligned.m8n8.x4.shared.b16 {%0,%1,%2,%3}, [%4];" \
        : "=r"(r0), "=r"(r1), "=r"(r2), "=r"(r3) : "r"(addr))
#define MMA16832_FP8(d, a, b) \
    asm volatile("mma.sync.aligned.m16n8k32.row.col.f32.e4m3.e4m3.f32 " \
        "{%0,%1,%2,%3},{%4,%5,%6,%7},{%8,%9},{%0,%1,%2,%3};" \
        : "+f"((d)[0]), "+f"((d)[1]), "+f"((d)[2]), "+f"((d)[3]) \
        : "r"((a)[0]), "r"((a)[1]), "r"((a)[2]), "r"((a)[3]), "r"((b)[0]), "r"((b)[1]))
#define CP_ASYNC16(dst, src) \
    asm volatile("cp.async.cg.shared.global [%0], [%1], 16;" :: "r"(dst), "l"(src))
#define CP_COMMIT() asm volatile("cp.async.commit_group;" ::: "memory")
#define CP_WAIT0()  asm volatile("cp.async.wait_group 0;" ::: "memory")

__device__ __forceinline__ uint16_t pack_e4m3x2(float hi, float lo) {
    uint16_t r;
    asm("cvt.rn.satfinite.e4m3x2.f32 %0, %1, %2;" : "=h"(r) : "f"(hi), "f"(lo));
    return r;
}

// dynamic smem layout for stage1 (bytes)
#define S_MERGE 0                    // 8 KB
#define S_A     8192                 // 64 KB A resident (128 x 512 e4m3, swizzled)
#define S_B0    (S_A + 65536)        // 73728, 16 KB
#define S_B1    (S_B0 + 16384)       // 90112, 16 KB
#define S_TOT   (S_B1 + 16384)       // 106496

// ---------------- fused convert + norm (sequential fadd(fmul) — validated R3) ----------------
__global__ void cvtnorm_kernel(const float* __restrict__ src, int which, float scale) {
    extern __shared__ float s[];               // [64][513]
    int r0 = blockIdx.x * 64;
    const float4* g4 = (const float4*)(src + (size_t)r0 * D_DIM);
    for (int u = threadIdx.x; u < 64 * 128; u += 256) {
        int row = u >> 7, c4 = u & 127;
        float4 v = g4[(size_t)row * 128 + c4];
        float* p = s + row * 513 + c4 * 4;
        p[0] = v.x; p[1] = v.y; p[2] = v.z; p[3] = v.w;
    }
    __syncthreads();
    // fp8 conversion from smem
    uint32_t* dst = (uint32_t*)(which ? (void*)g_Xq : (void*)g_Wq) + (size_t)r0 * 128;
    for (int i = threadIdx.x; i < 64 * 128; i += 256) {
        int row = i >> 7, c4 = i & 127;
        const float* p = s + row * 513 + c4 * 4;
        uint32_t lo = pack_e4m3x2(p[1] * scale, p[0] * scale);
        uint32_t hi = pack_e4m3x2(p[3] * scale, p[2] * scale);
        dst[(size_t)row * 128 + c4] = lo | (hi << 16);
    }
    // exact sequential norm per row
    if (threadIdx.x < 64) {
        const float* p = s + threadIdx.x * 513;
        float acc = 0.f;
        #pragma unroll 8
        for (int i = 0; i < D_DIM; i++)
            acc = __fadd_rn(acc, __fmul_rn(p[i], p[i]));
        if (which) g_xnorm[r0 + threadIdx.x] = acc;
        else       g_wnorm[r0 + threadIdx.x] = acc;
    }
}

// ---------------- stage1: fp8 mma.sync GEMM, balanced persistent split ----------------
__device__ __forceinline__ void issue_chunk2(uint32_t sb, int tid, int t, int kc, int buf) {
    const uint8_t* src = g_Wq + (size_t)(t * 128) * D_DIM + kc * 128;
    uint32_t bufaddr = sb + (buf ? S_B1 : S_B0);
    #pragma unroll
    for (int i = 0; i < 2; i++) {
        int unit = i * 512 + tid;            // 1024 16B units
        int nrow = unit >> 3, u = unit & 7;
        uint32_t dst = bufaddr + nrow * 128 + ((u ^ (nrow & 7)) << 4);
        const void* gsrc = src + (size_t)nrow * D_DIM + u * 16;
        CP_ASYNC16(dst, gsrc);
    }
    CP_COMMIT();
}

#define CE(i, j) { if (d[j] < d[i]) { float td = d[i]; d[i] = d[j]; d[j] = td; \
                                      int ti = ix[i]; ix[i] = ix[j]; ix[j] = ti; } }

__global__ void __launch_bounds__(512, 1) stage1_kernel() {
    extern __shared__ char smem[];
    const uint32_t sb = smem_to_u32(smem);
    const int tid = threadIdx.x;
    const int lane = tid & 31;
    const int w = tid >> 5;                // 16 warps
    const int wm = w & 3, wn = w >> 2;     // warp tile: rows wm*32, cols wn*32

    // static balanced item split
    const int G = gridDim.x, cta = blockIdx.x;
    const int qq = NITEM / G, rr = NITEM - qq * G;
    const int start = cta * qq + (cta < rr ? cta : rr);
    const int count = qq + (cta < rr ? 1 : 0);

    // per-lane ldmatrix addressing (byte layout validated R6/R8)
    const int a_row = (lane & 7) + ((lane >> 3) & 1) * 8;
    const int a_kh  = (lane >> 4) & 1;
    uint32_t a_base[2]; int a_x[2];
    #pragma unroll
    for (int mt = 0; mt < 2; mt++) {
        int r = wm * 32 + mt * 16 + a_row;
        a_base[mt] = sb + S_A + r * 512;
        a_x[mt] = r & 7;
    }
    const int b_row_in = (lane & 7) + ((lane >> 4) & 1) * 8;
    const int b_kh     = (lane >> 3) & 1;
    uint32_t b_rowoff[2]; int b_x[2];
    #pragma unroll
    for (int p = 0; p < 2; p++) {
        int nr = wn * 32 + p * 16 + b_row_in;
        b_rowoff[p] = nr * 128;
        b_x[p] = nr & 7;
    }
    const int tg = lane & 3, g8 = lane >> 2;

    int cur_m = -1;
    for (int itm = start; itm < start + count; itm++) {
        const int mt_tile = itm >> 3, grp = itm & 7;
        const int m0 = mt_tile * 128;

        // prologue B chunk for this item (overlaps A reload)
        issue_chunk2(sb, tid, grp * 4, 0, 0);

        if (mt_tile != cur_m) {
            cur_m = mt_tile;
            __syncthreads();           // all warps done reading previous A
            const uint8_t* Xr = g_Xq + (size_t)m0 * D_DIM;
            #pragma unroll 4
            for (int ld = 0; ld < 8; ld++) {
                int unit = ld * 512 + tid;           // 4096 16B units
                int r = unit >> 5, u = unit & 31;
                uint4 v = *(const uint4*)(Xr + (size_t)r * D_DIM + u * 16);
                *(uint4*)(smem + S_A + r * 512 + ((u ^ (r & 7)) << 4)) = v;
            }
            __syncthreads();
        }

        for (int tt = 0; tt < 4; tt++) {
            const int t = grp * 4 + tt;
            float acc[2][4][4];
            #pragma unroll
            for (int mt = 0; mt < 2; mt++)
                #pragma unroll
                for (int nt = 0; nt < 4; nt++)
                    #pragma unroll
                    for (int e = 0; e < 4; e++) acc[mt][nt][e] = 0.f;

            for (int kc = 0; kc < 4; kc++) {
                int ch = tt * 4 + kc;
                CP_WAIT0();
                __syncthreads();
                if (ch + 1 < 16)
                    issue_chunk2(sb, tid, grp * 4 + ((ch + 1) >> 2), (ch + 1) & 3,
                                 (ch + 1) & 1);
                uint32_t bbuf = sb + ((ch & 1) ? S_B1 : S_B0);
                #pragma unroll
                for (int s = 0; s < 4; s++) {           // 4 k32-steps per 128-k chunk
                    int gk = kc * 4 + s;                 // global k32 index 0..15
                    uint32_t a[2][4];
                    #pragma unroll
                    for (int mt = 0; mt < 2; mt++) {
                        int u = gk * 2 + a_kh;
                        LDSM_X4(a[mt][0], a[mt][1], a[mt][2], a[mt][3],
                                a_base[mt] + ((u ^ a_x[mt]) << 4));
                    }
                    uint32_t b[4][2];
                    #pragma unroll
                    for (int p = 0; p < 2; p++) {
                        int u = s * 2 + b_kh;
                        uint32_t r0, r1, r2, r3;
                        LDSM_X4(r0, r1, r2, r3, bbuf + b_rowoff[p] + ((u ^ b_x[p]) << 4));
                        b[2 * p][0] = r0; b[2 * p][1] = r1;
                        b[2 * p + 1][0] = r2; b[2 * p + 1][1] = r3;
                    }
                    #pragma unroll
                    for (int mt = 0; mt < 2; mt++)
                        #pragma unroll
                        for (int nt = 0; nt < 4; nt++)
                            MMA16832_FP8(acc[mt][nt], a[mt], b[nt]);
                }
            }

            // ---- per-quadrant (32 codes) top-2 epilogue ----
            float wn8[8];
            #pragma unroll
            for (int nt = 0; nt < 4; nt++)
                #pragma unroll
                for (int e = 0; e < 2; e++)
                    wn8[nt * 2 + e] = g_wnorm[t * 128 + wn * 32 + nt * 8 + tg * 2 + e];

            #pragma unroll
            for (int mt = 0; mt < 2; mt++) {
                #pragma unroll
                for (int h = 0; h < 2; h++) {
                    float v1 = 3.4e38f, v2 = 3.4e38f; int i1 = 0, i2 = 0;
                    #pragma unroll
                    for (int nt = 0; nt < 4; nt++) {
                        #pragma unroll
                        for (int e = 0; e < 2; e++) {
                            int code = t * 128 + wn * 32 + nt * 8 + tg * 2 + e;
                            float dd = __fmaf_rn(-2.0f * DEQ, acc[mt][nt][h * 2 + e],
                                                 wn8[nt * 2 + e]);
                            if (dd < v2) {
                                if (dd < v1) { v2 = v1; i2 = i1; v1 = dd; i1 = code; }
                                else         { v2 = dd; i2 = code; }
                            }
                        }
                    }
                    #pragma unroll
                    for (int off = 1; off <= 2; off <<= 1) {
                        float w1 = __shfl_xor_sync(0xffffffffu, v1, off);
                        int   j1 = __shfl_xor_sync(0xffffffffu, i1, off);
                        float w2 = __shfl_xor_sync(0xffffffffu, v2, off);
                        int   j2 = __shfl_xor_sync(0xffffffffu, i2, off);
                        if (w1 < v1) {
                            float nv2; int ni2;
                            if (v1 < w2) { nv2 = v1; ni2 = i1; } else { nv2 = w2; ni2 = j2; }
                            v1 = w1; i1 = j1; v2 = nv2; i2 = ni2;
                        } else if (w1 < v2) { v2 = w1; i2 = j1; }
                    }
                    if (tg == 0) {
                        int row = wm * 32 + mt * 16 + h * 8 + g8;
                        ((float4*)(smem + S_MERGE))[row * 4 + wn] =
                            make_float4(v1, __int_as_float(i1), v2, __int_as_float(i2));
                    }
                }
            }
            __syncthreads();
            if (tid < 128) {
                float d[8]; int ix[8];
                #pragma unroll
                for (int q = 0; q < 4; q++) {
                    float4 r = ((float4*)(smem + S_MERGE))[tid * 4 + q];
                    d[2 * q]     = r.x; ix[2 * q]     = __float_as_int(r.y);
                    d[2 * q + 1] = r.z; ix[2 * q + 1] = __float_as_int(r.w);
                }
                CE(0,1) CE(2,3) CE(4,5) CE(6,7)
                CE(0,2) CE(1,3) CE(4,6) CE(5,7)
                CE(1,2) CE(5,6)
                CE(0,4) CE(1,5) CE(2,6) CE(3,7)
                CE(2,4) CE(3,5)
                CE(1,2) CE(3,4) CE(5,6)
                size_t base = ((size_t)(m0 + tid) * NT + t) * 2;
                g_cand[base]     = make_float4(d[0], __int_as_float(ix[0]),
                                               d[1], __int_as_float(ix[1]));
                g_cand[base + 1] = make_float4(d[2], __int_as_float(ix[2]),
                                               d[3], __int_as_float(ix[3]));
            }
            __syncthreads();
        }
    }
}

// ---------------- stage 2 (fused): top-8 rescore + quantized_st + loss + hist ----------------
__global__ void __launch_bounds__(256) stage2_kernel(const float* __restrict__ X,
                                                     const float* __restrict__ W,
                                                     float* __restrict__ out_q,
                                                     float* __restrict__ out_loss,
                                                     float* __restrict__ out_idx,
                                                     int write_loss, int write_idx) {
    const int warp = threadIdx.x >> 5, lane = threadIdx.x & 31;
    const int token = blockIdx.x * 8 + warp;
    const unsigned FULL = 0xffffffffu;

    size_t cbase = ((size_t)token * NT + lane) * 2;
    float4 ca = g_cand[cbase];
    float4 cb = g_cand[cbase + 1];
    float cd0 = ca.x; int ci0 = __float_as_int(ca.y);
    float cd1 = ca.z; int ci1 = __float_as_int(ca.w);
    float cd2 = cb.x; int ci2 = __float_as_int(cb.y);
    float cd3 = cb.z; int ci3 = __float_as_int(cb.w);

    float xr[16];
    const float* x = X + (size_t)token * D_DIM;
    #pragma unroll
    for (int j = 0; j < 4; j++) {
        float4 v = *(const float4*)(x + j * 128 + lane * 4);
        xr[j * 4 + 0] = v.x; xr[j * 4 + 1] = v.y; xr[j * 4 + 2] = v.z; xr[j * 4 + 3] = v.w;
    }
    float xn = g_xnorm[token];
    float bd = 3.4e38f; int bi = 0x7fffffff;

    #pragma unroll
    for (int s = 0; s < 8; s++) {
        float md = fminf(fminf(cd0, cd1), fminf(cd2, cd3));
        float m = md;
        #pragma unroll
        for (int o = 16; o > 0; o >>= 1) m = fminf(m, __shfl_xor_sync(FULL, m, o));
        unsigned ball = __ballot_sync(FULL, md == m);
        int src = __ffs(ball) - 1;
        int pick = 0;
        if (lane == src) {
            if (cd0 == md)      { pick = ci0; cd0 = 3.4e38f; }
            else if (cd1 == md) { pick = ci1; cd1 = 3.4e38f; }
            else if (cd2 == md) { pick = ci2; cd2 = 3.4e38f; }
            else                { pick = ci3; cd3 = 3.4e38f; }
        }
        pick = __shfl_sync(FULL, pick, src);

        const float* wv = W + (size_t)pick * D_DIM;
        float acc = 0.f;
        #pragma unroll
        for (int j = 0; j < 4; j++) {
            float4 v = *(const float4*)(wv + j * 128 + lane * 4);
            acc = __fmaf_rn(xr[j * 4 + 0], v.x, acc);
            acc = __fmaf_rn(xr[j * 4 + 1], v.y, acc);
            acc = __fmaf_rn(xr[j * 4 + 2], v.z, acc);
            acc = __fmaf_rn(xr[j * 4 + 3], v.w, acc);
        }
        #pragma unroll
        for (int o = 16; o > 0; o >>= 1) acc += __shfl_xor_sync(FULL, acc, o);
        float dd = __fsub_rn(__fadd_rn(xn, g_wnorm[pick]), 2.0f * acc);
        if (dd < bd || (dd == bd && pick < bi)) { bd = dd; bi = pick; }
    }

    // fused epilogue: quantized_st + loss + histogram (all lanes agree on bi)
    const float* wv = W + (size_t)bi * D_DIM;
    float s = 0.f;
    #pragma unroll
    for (int j = 0; j < 4; j++) {
        float4 qv = *(const float4*)(wv + j * 128 + lane * 4);
        float dx = __fsub_rn(qv.x, xr[j * 4 + 0]);
        float dy = __fsub_rn(qv.y, xr[j * 4 + 1]);
        float dz = __fsub_rn(qv.z, xr[j * 4 + 2]);
        float dw = __fsub_rn(qv.w, xr[j * 4 + 3]);
        float4 st;
        st.x = __fadd_rn(xr[j * 4 + 0], dx);
        st.y = __fadd_rn(xr[j * 4 + 1], dy);
        st.z = __fadd_rn(xr[j * 4 + 2], dz);
        st.w = __fadd_rn(xr[j * 4 + 3], dw);
        *(float4*)(out_q + (size_t)token * D_DIM + j * 128 + lane * 4) = st;
        s += dx * dx + dy * dy + dz * dz + dw * dw;
    }
    #pragma unroll
    for (int o = 16; o > 0; o >>= 1) s += __shfl_xor_sync(FULL, s, o);
    if (lane == 0) {
        g_indices[token] = bi;
        if (write_loss) out_loss[token] = 1.25f * s * (1.0f / D_DIM);
        if (write_idx)  out_idx[token] = (float)bi;
        atomicAdd(&g_counts[bi], 1);
    }
}

// ---------------- zero counts / perplexity ----------------
__global__ void zero_counts_kernel() {
    int i = blockIdx.x * blockDim.x + threadIdx.x;
    if (i < K_CODES) g_counts[i] = 0;
}
__global__ void perplexity_kernel(float* __restrict__ out_perp, int M) {
    __shared__ float ws[32];
    float inv = 1.0f / (float)M;
    float s = 0.f;
    for (int i = threadIdx.x; i < K_CODES; i += blockDim.x) {
        float p = (float)g_counts[i] * inv;
        s += p * logf(p + 1e-10f);
    }
    #pragma unroll
    for (int o = 16; o > 0; o >>= 1) s += __shfl_down_sync(0xffffffffu, s, o);
    if ((threadIdx.x & 31) == 0) ws[threadIdx.x >> 5] = s;
    __syncthreads();
    if (threadIdx.x == 0) {
        float tot = 0.f;
        int nw = blockDim.x >> 5;
        for (int w = 0; w < nw; w++) tot += ws[w];
        *out_perp = expf(-tot);
    }
}

// ---------------- launch ----------------
extern "C" void kernel_launch(void* const* d_in, const int* in_sizes, int n_in,
                              void* d_out, int out_size)
{
    const float* X = (const float*)d_in[0];   // flat_input [32768, 512]
    const float* W = (const float*)d_in[1];   // weight [4096, 512]
    const int M = in_sizes[0] / D_DIM;

    float* out = (float*)d_out;
    float* out_q = out;
    size_t base = (size_t)M * D_DIM;
    int has_loss = out_size >= (int)(base + M);
    int has_perp = out_size >= (int)(base + M + 1);
    int has_idx  = out_size >= (int)(base + 2 * M + 1);
    float* out_loss = out + base;
    float* out_perp = out_loss + M;
    float* out_idx  = out_perp + 1;

    int nsm = 148;
    cudaDeviceGetAttribute(&nsm, cudaDevAttrMultiProcessorCount, 0);
    if (nsm <= 0) nsm = 148;

    cudaFuncSetAttribute(stage1_kernel, cudaFuncAttributeMaxDynamicSharedMemorySize, S_TOT);
    cudaFuncSetAttribute(cvtnorm_kernel, cudaFuncAttributeMaxDynamicSharedMemorySize,
                         64 * 513 * 4);

    cvtnorm_kernel<<<M / 64, 256, 64 * 513 * 4>>>(X, 1, SX);       // X -> fp8 + xnorm
    cvtnorm_kernel<<<K_CODES / 64, 256, 64 * 513 * 4>>>(W, 0, SW); // W -> fp8 + wnorm
    zero_counts_kernel<<<(K_CODES + 255) / 256, 256>>>();
    stage1_kernel<<<nsm, 512, S_TOT>>>();
    stage2_kernel<<<M / 8, 256>>>(X, W, out_q,
                                  has_loss ? out_loss : out_q,
                                  has_idx ? out_idx : out_q,
                                  has_loss, has_idx);
    if (has_perp) perplexity_kernel<<<1, 1024>>>(out_perp, M);
}